// round 1
// baseline (speedup 1.0000x reference)
#include <cuda_runtime.h>
#include <math.h>

// ---------------------------------------------------------------------------
// CoreLstm: 3-layer LayerNorm-LSTM
//   T=32, B=256, HID=384, 4H=1536, D_IN=1152
// Structure:
//   per layer l:
//     xg = LN(x @ wx_l; gxw,gxb)          (big parallel GEMM + row-LN)
//     for t in 0..31:
//       hraw = h @ wh_l                   (small GEMM, sequential)
//       gate = xg[t] + LN(hraw; ghw,ghb) + bias
//       i,f,o,u = split(gate); c = sig(f)*c + sig(i)*tanh(u); h = sig(o)*tanh(c)
//       out[t] = h  (feeds next layer / final output)
// Output: [output (T,B,H)] ++ [Hn (L,B,H)] ++ [Cn (L,B,H)]
// ---------------------------------------------------------------------------

#define T_STEPS 32
#define BATCH   256
#define HIDDEN  384
#define G4      1536
#define DIN     1152
#define NROWS   (T_STEPS * BATCH)     // 8192
#define LN_EPS  1e-5f

#define OUT_OUTPUT 0
#define OUT_HN     (T_STEPS * BATCH * HIDDEN)            // 3145728
#define OUT_CN     (OUT_HN + 3 * BATCH * HIDDEN)         // 3440640

// Scratch (device globals: no allocation allowed)
__device__ float g_x0[NROWS * DIN];      // concat input for layer 0   (37.7 MB)
__device__ float g_x [NROWS * HIDDEN];   // inter-layer activations    (12.6 MB)
__device__ float g_xg[NROWS * G4];       // LN(x @ wx)                 (50.3 MB)
__device__ float g_hraw[BATCH * G4];     // h @ wh per step            (1.6 MB)
__device__ float g_h[BATCH * HIDDEN];
__device__ float g_c[BATCH * HIDDEN];

// ---------------------------------------------------------------------------
// concat [ent|spa|sca] -> x0 [8192, 1152]
// ---------------------------------------------------------------------------
__global__ void concat_kernel(const float* __restrict__ ent,
                              const float* __restrict__ spa,
                              const float* __restrict__ sca,
                              float* __restrict__ x0) {
    int total = NROWS * DIN;
    for (int idx = blockIdx.x * blockDim.x + threadIdx.x; idx < total;
         idx += gridDim.x * blockDim.x) {
        int r = idx / DIN;
        int c = idx - r * DIN;
        float v;
        if (c < 256)       v = ent[r * 256 + c];
        else if (c < 512)  v = spa[r * 256 + (c - 256)];
        else               v = sca[r * 640 + (c - 512)];
        x0[idx] = v;
    }
}

// ---------------------------------------------------------------------------
// Tiled SGEMM: C[M,N] = A[M,K] @ B[K,N], all row-major, fp32.
// BN=64, BK=16, 256 threads (16x16), thread micro-tile TM x 4.
// Requires: M % BM == 0, N % 64 == 0, K % 16 == 0 (all hold here).
// ---------------------------------------------------------------------------
template<int BM, int TM>
__global__ void sgemm_kernel(const float* __restrict__ A,
                             const float* __restrict__ B,
                             float* __restrict__ C,
                             int M, int N, int K) {
    constexpr int BN = 64, BK = 16, TN = 4;
    __shared__ __align__(16) float As[BK][BM];
    __shared__ __align__(16) float Bs[BK][BN];

    const int tid = threadIdx.x;                // 256 threads
    const int tx = tid & 15, ty = tid >> 4;
    const int row0 = blockIdx.y * BM + ty * TM;
    const int col0 = blockIdx.x * BN + tx * TN;

    float acc[TM][TN];
    #pragma unroll
    for (int i = 0; i < TM; i++)
        #pragma unroll
        for (int j = 0; j < TN; j++) acc[i][j] = 0.f;

    const int aRow = tid >> 2;                  // 0..63
    const int aK   = (tid & 3) << 2;            // 0,4,8,12
    const int bRow = tid >> 4;                  // 0..15
    const int bCol = (tid & 15) << 2;           // 0..60

    const float* Abase = A + (size_t)blockIdx.y * BM * K;
    const float* Bbase = B + blockIdx.x * BN;

    for (int k0 = 0; k0 < K; k0 += BK) {
        if (aRow < BM) {
            float4 av = *reinterpret_cast<const float4*>(Abase + (size_t)aRow * K + k0 + aK);
            As[aK + 0][aRow] = av.x;
            As[aK + 1][aRow] = av.y;
            As[aK + 2][aRow] = av.z;
            As[aK + 3][aRow] = av.w;
        }
        *reinterpret_cast<float4*>(&Bs[bRow][bCol]) =
            *reinterpret_cast<const float4*>(Bbase + (size_t)(k0 + bRow) * N + bCol);
        __syncthreads();

        #pragma unroll
        for (int k = 0; k < BK; k++) {
            float a[TM];
            #pragma unroll
            for (int i = 0; i < TM; i++) a[i] = As[k][ty * TM + i];
            float4 bv = *reinterpret_cast<const float4*>(&Bs[k][tx * TN]);
            float bb[TN] = {bv.x, bv.y, bv.z, bv.w};
            #pragma unroll
            for (int i = 0; i < TM; i++)
                #pragma unroll
                for (int j = 0; j < TN; j++)
                    acc[i][j] = fmaf(a[i], bb[j], acc[i][j]);
        }
        __syncthreads();
    }

    #pragma unroll
    for (int i = 0; i < TM; i++) {
        float4 cv = make_float4(acc[i][0], acc[i][1], acc[i][2], acc[i][3]);
        *reinterpret_cast<float4*>(C + (size_t)(row0 + i) * N + col0) = cv;
    }
}

// ---------------------------------------------------------------------------
// block-wide sum of (s, s2) for NW warps
// ---------------------------------------------------------------------------
template<int NW>
__device__ __forceinline__ float2 block_sum2(float s, float s2) {
    __shared__ float sh[2 * NW];
    const int lane = threadIdx.x & 31;
    const int wid  = threadIdx.x >> 5;
    #pragma unroll
    for (int o = 16; o > 0; o >>= 1) {
        s  += __shfl_down_sync(0xffffffffu, s, o);
        s2 += __shfl_down_sync(0xffffffffu, s2, o);
    }
    if (lane == 0) { sh[wid] = s; sh[NW + wid] = s2; }
    __syncthreads();
    if (wid == 0) {
        s  = (lane < NW) ? sh[lane] : 0.f;
        s2 = (lane < NW) ? sh[NW + lane] : 0.f;
        #pragma unroll
        for (int o = 16; o > 0; o >>= 1) {
            s  += __shfl_down_sync(0xffffffffu, s, o);
            s2 += __shfl_down_sync(0xffffffffu, s2, o);
        }
        if (lane == 0) { sh[0] = s; sh[NW] = s2; }
    }
    __syncthreads();
    return make_float2(sh[0], sh[NW]);
}

// ---------------------------------------------------------------------------
// In-place row LayerNorm over N=1536: x = (x - mu) * rsqrt(var+eps) * g + b
// one block per row, 256 threads, 6 elems each
// ---------------------------------------------------------------------------
__global__ void ln_rows_kernel(float* __restrict__ X,
                               const float* __restrict__ gam,
                               const float* __restrict__ bet) {
    float* x = X + (size_t)blockIdx.x * G4;
    const int tid = threadIdx.x;   // 256
    float v[6];
    float s = 0.f, s2 = 0.f;
    #pragma unroll
    for (int q = 0; q < 6; q++) {
        v[q] = x[tid + q * 256];
        s += v[q];
        s2 = fmaf(v[q], v[q], s2);
    }
    float2 r2 = block_sum2<8>(s, s2);
    const float inv = 1.0f / (float)G4;
    float mu  = r2.x * inv;
    float var = fmaf(-mu, mu, r2.y * inv);
    float r   = rsqrtf(var + LN_EPS);
    #pragma unroll
    for (int q = 0; q < 6; q++) {
        int c = tid + q * 256;
        x[c] = fmaf((v[q] - mu) * r, gam[c], bet[c]);
    }
}

// ---------------------------------------------------------------------------
// One LSTM timestep: LN(hraw) + gates + state update.
// one block per batch row (256 blocks), 384 threads (thread = hid index)
// ---------------------------------------------------------------------------
__global__ void lstm_step_kernel(const float* __restrict__ hraw,   // [256,1536]
                                 const float* __restrict__ xg_t,   // [256,1536]
                                 const float* __restrict__ bias,   // [1536]
                                 const float* __restrict__ ghw,    // [1536]
                                 const float* __restrict__ ghb,    // [1536]
                                 float* __restrict__ h,            // [256,384]
                                 float* __restrict__ c,            // [256,384]
                                 float* __restrict__ out_t) {      // [256,384]
    const int b = blockIdx.x;
    const int i = threadIdx.x;   // 0..383
    const float* hr = hraw + (size_t)b * G4;

    float v[4];
    float s = 0.f, s2 = 0.f;
    #pragma unroll
    for (int q = 0; q < 4; q++) {
        v[q] = hr[i + q * HIDDEN];
        s += v[q];
        s2 = fmaf(v[q], v[q], s2);
    }
    float2 r2 = block_sum2<12>(s, s2);
    const float inv = 1.0f / (float)G4;
    float mu  = r2.x * inv;
    float var = fmaf(-mu, mu, r2.y * inv);
    float r   = rsqrtf(var + LN_EPS);

    float gate[4];
    #pragma unroll
    for (int q = 0; q < 4; q++) {
        int col = i + q * HIDDEN;
        float lnv = fmaf((v[q] - mu) * r, ghw[col], ghb[col]);
        gate[q] = xg_t[(size_t)b * G4 + col] + lnv + bias[col];
    }
    float ig = 1.f / (1.f + expf(-gate[0]));
    float fg = 1.f / (1.f + expf(-gate[1]));
    float og = 1.f / (1.f + expf(-gate[2]));
    float ug = tanhf(gate[3]);

    int idx = b * HIDDEN + i;
    float cn = fmaf(fg, c[idx], ig * ug);
    float hn = og * tanhf(cn);
    c[idx] = cn;
    h[idx] = hn;
    out_t[idx] = hn;
}

// ---------------------------------------------------------------------------
__global__ void copy_vec_kernel(const float* __restrict__ src,
                                float* __restrict__ dst, int n) {
    for (int i = blockIdx.x * blockDim.x + threadIdx.x; i < n;
         i += gridDim.x * blockDim.x)
        dst[i] = src[i];
}

// ---------------------------------------------------------------------------
extern "C" void kernel_launch(void* const* d_in, const int* in_sizes, int n_in,
                              void* d_out, int out_size) {
    const float* ent  = (const float*)d_in[0];
    const float* spa  = (const float*)d_in[1];
    const float* sca  = (const float*)d_in[2];
    const float* h0   = (const float*)d_in[3];
    const float* c0   = (const float*)d_in[4];
    const float* wx0  = (const float*)d_in[5];
    const float* wx1  = (const float*)d_in[6];
    const float* wx2  = (const float*)d_in[7];
    const float* wh   = (const float*)d_in[8];
    const float* bias = (const float*)d_in[9];
    const float* gxw  = (const float*)d_in[10];
    const float* gxb  = (const float*)d_in[11];
    const float* ghw  = (const float*)d_in[12];
    const float* ghb  = (const float*)d_in[13];
    float* out = (float*)d_out;

    float *x0, *x, *xg, *hraw, *h, *c;
    cudaGetSymbolAddress((void**)&x0,   g_x0);
    cudaGetSymbolAddress((void**)&x,    g_x);
    cudaGetSymbolAddress((void**)&xg,   g_xg);
    cudaGetSymbolAddress((void**)&hraw, g_hraw);
    cudaGetSymbolAddress((void**)&h,    g_h);
    cudaGetSymbolAddress((void**)&c,    g_c);

    concat_kernel<<<1024, 256>>>(ent, spa, sca, x0);

    const float* wx_l[3] = {wx0, wx1, wx2};
    const int    K_l[3]  = {DIN, HIDDEN, HIDDEN};

    for (int l = 0; l < 3; l++) {
        const float* A = (l == 0) ? x0 : x;
        // xg = x @ wx_l  -> LN
        dim3 g1(G4 / 64, NROWS / 64);
        sgemm_kernel<64, 4><<<g1, 256>>>(A, wx_l[l], xg, NROWS, G4, K_l[l]);
        ln_rows_kernel<<<NROWS, 256>>>(xg, gxw + l * G4, gxb + l * G4);

        // init state
        copy_vec_kernel<<<96, 512>>>(h0 + l * BATCH * HIDDEN, h, BATCH * HIDDEN);
        copy_vec_kernel<<<96, 512>>>(c0 + l * BATCH * HIDDEN, c, BATCH * HIDDEN);

        float* outbuf = (l == 2) ? (out + OUT_OUTPUT) : x;
        const float* wh_l = wh + (size_t)l * HIDDEN * G4;

        for (int t = 0; t < T_STEPS; t++) {
            dim3 g2(G4 / 64, BATCH / 32);
            sgemm_kernel<32, 2><<<g2, 256>>>(h, wh_l, hraw, BATCH, G4, HIDDEN);
            lstm_step_kernel<<<BATCH, HIDDEN>>>(
                hraw, xg + (size_t)t * BATCH * G4,
                bias + l * G4, ghw + l * G4, ghb + l * G4,
                h, c, outbuf + (size_t)t * BATCH * HIDDEN);
        }
        copy_vec_kernel<<<96, 512>>>(h, out + OUT_HN + l * BATCH * HIDDEN, BATCH * HIDDEN);
        copy_vec_kernel<<<96, 512>>>(c, out + OUT_CN + l * BATCH * HIDDEN, BATCH * HIDDEN);
    }
}